// round 11
// baseline (speedup 1.0000x reference)
#include <cuda_runtime.h>

// ---------------------------------------------------------------------------
// MogrifierRNN persistent kernel, round 10.
//   - 16x32 block tile (8 rowgroups x 16 colgroups): lane-pair A broadcast
//     halves mog smem reads; rowgroups fully independent across the sequence
//   - 16-block direct-poll barriers (no leader round-trip)
//   - gates reuses P4's A tile (xx) -- no stage/wait in the longest phase
//   - cp.async weight ring w/ cross-barrier prefetch; FFMA2; reg-resident c/h
// ---------------------------------------------------------------------------

#define S_LEN 512
#define B_DIM 128
#define HID   512
#define K_RANK 256
#define NQP   2

#define GRID_BLOCKS 128
#define NT          256
#define APITCH      516                  // conflict-free LDS.128 pitch
#define ABUF        (16 * APITCH)        // 8256 floats = 33,024 B
#define WSLOT_F     2048                 // slot: 8KB (gates); mog uses first 4KB
#define WWARP_F     (2 * WSLOT_F)
#define WRING_F     (8 * WWARP_F)        // 128KB
#define SMEM_FLOATS (2 * ABUF + WRING_F) // 49280
#define SMEM_BYTES  (SMEM_FLOATS * 4)    // 197,120 B
#define BAR_STRIDE  32

typedef unsigned long long u64;

// ------------------------- device scratch ----------------------------------
__device__ float g_Q[NQP * HID * HID];   // Q[i][m][n]
__device__ float g_R[NQP * HID * HID];   // R[i][n][m]
__device__ float g_xx[B_DIM * HID];
__device__ float g_h[2][B_DIM * HID];
__device__ unsigned int g_arrive[GRID_BLOCKS * BAR_STRIDE];
__device__ unsigned int g_go_full;

__global__ void mg_init() {
    int i = (int)threadIdx.x;
    if (i < GRID_BLOCKS) g_arrive[i * BAR_STRIDE] = 0u;
    if (i == 0) g_go_full = 0u;
}

__device__ __forceinline__ float sigf(float v) {
    return 1.0f / (1.0f + __expf(-v));
}

// ---- packed fp32x2 FMA ------------------------------------------------------
union F4 { float4 f; ulonglong2 d; };

__device__ __forceinline__ void ffma2(u64& acc, u64 a, u64 b) {
    asm("fma.rn.f32x2 %0, %1, %2, %0;" : "+l"(acc) : "l"(a), "l"(b));
}
__device__ __forceinline__ float pairsum(u64 p) {
    return __uint_as_float((unsigned)p) + __uint_as_float((unsigned)(p >> 32));
}

// ---- cp.async ---------------------------------------------------------------
__device__ __forceinline__ void cpa16(float* dst_smem, const float* src) {
    unsigned d = (unsigned)__cvta_generic_to_shared(dst_smem);
    asm volatile("cp.async.cg.shared.global [%0], [%1], 16;"
                 :: "r"(d), "l"(src) : "memory");
}
__device__ __forceinline__ void cp_commit() {
    asm volatile("cp.async.commit_group;" ::: "memory");
}
template <int N> __device__ __forceinline__ void cp_waitg() {
    asm volatile("cp.async.wait_group %0;" :: "n"(N) : "memory");
}

// ---- barriers ---------------------------------------------------------------
__device__ __forceinline__ unsigned int ld_acq(const unsigned int* p) {
    unsigned int v;
    asm volatile("ld.acquire.gpu.global.u32 %0, [%1];"
                 : "=r"(v) : "l"(p) : "memory");
    return v;
}
__device__ __forceinline__ void st_rel(unsigned int* p, unsigned int v) {
    asm volatile("st.release.gpu.global.u32 [%0], %1;"
                 :: "l"(p), "r"(v) : "memory");
}

// Row-group barrier: the 16 blocks with the same (blockIdx.x & 7).
// Direct-poll: every block arrives, 16 threads poll the 16 member flags.
__device__ __forceinline__ void row_barrier(unsigned int& epoch, int rt) {
    epoch++;
    __syncthreads();
    if (threadIdx.x == 0) st_rel(&g_arrive[blockIdx.x * BAR_STRIDE], epoch);
    if (threadIdx.x < 16) {
        while (ld_acq(&g_arrive[(rt + 8 * threadIdx.x) * BAR_STRIDE]) < epoch) { }
    }
    __syncthreads();
}

// Full-grid barrier (once, after precompute).
__device__ __forceinline__ void full_barrier(unsigned int& epoch) {
    epoch++;
    __syncthreads();
    if (blockIdx.x == 0) {
        if (threadIdx.x == 0) st_rel(&g_arrive[0], epoch);
        if (threadIdx.x < GRID_BLOCKS) {
            while (ld_acq(&g_arrive[threadIdx.x * BAR_STRIDE]) < epoch) { }
        }
        __syncthreads();
        if (threadIdx.x == 0) st_rel(&g_go_full, epoch);
    } else {
        if (threadIdx.x == 0) {
            st_rel(&g_arrive[blockIdx.x * BAR_STRIDE], epoch);
            while (ld_acq(&g_go_full) < epoch) { }
        }
        __syncthreads();
    }
}

// ---- staging ----------------------------------------------------------------
// A k-half: rows [r0,r0+16) x k[256h,256h+256). One group; 4 cpa16/thread.
__device__ __forceinline__ void stageA_half(float* As, const float* A,
                                            int r0, int half, int tid) {
#pragma unroll
    for (int i = 0; i < 4; i++) {
        int e = i * NT + tid;            // 0..1023 f4
        int row = e >> 6, q = e & 63;
        cpa16(As + row * APITCH + half * 256 + q * 4,
              A + (r0 + row) * HID + half * 256 + q * 4);
    }
    cp_commit();
}
// A full tile (gates h): one group; 8 cpa16/thread.
__device__ __forceinline__ void stageA_full(float* As, const float* A,
                                            int r0, int tid) {
#pragma unroll
    for (int i = 0; i < 8; i++) {
        int e = i * NT + tid;            // 0..2047 f4
        int row = e >> 7, q = e & 127;
        cpa16(As + row * APITCH + q * 4, A + (r0 + row) * HID + q * 4);
    }
    cp_commit();
}

// Mog W prefetch: this warp's 4 col rows, k split in 2 slots (2 groups).
// Slot s: row rr (0..3) at f4 [rr*64, rr*64+64), k = [256s, 256s+256).
__device__ __forceinline__ void mogw_issue(float* myW, const float* W,
                                           int jbase, int lane) {
#pragma unroll
    for (int s = 0; s < 2; s++) {
        float* slot = myW + s * WSLOT_F;
#pragma unroll
        for (int i = 0; i < 8; i++) {
            int f = lane + 32 * i;       // 0..255 f4
            int rr = f >> 6, q = f & 63;
            cpa16(slot + f * 4, W + (jbase + rr) * HID + s * 256 + q * 4);
        }
        cp_commit();
    }
}

// Gates W chunk: 16 rows (4 gates x 4 cols) x 128 k. One group; 16/lane.
// Slot: row rr = g*4+cc at f4 [rr*32, rr*32+32).
__device__ __forceinline__ void gw_issue(float* slot, const float* Wsrc,
                                         int jbase, int kc, int lane) {
#pragma unroll
    for (int i = 0; i < 16; i++) {
        int f = lane + 32 * i;           // 0..511 f4
        int rr = f >> 5, q = f & 31;
        int g = rr >> 2, cc = rr & 3;
        cpa16(slot + f * 4, Wsrc + (g * HID + jbase + cc) * HID + kc + q * 4);
    }
    cp_commit();
}

// Mogrifier phase. Entering: this phase's W (2 groups) already issued.
__device__ __forceinline__ void mog_phase(float* As, float* myW,
                                          const float* Aglob, int r0,
                                          int lane, int tid,
                                          float mulA, float mulB,
                                          float& resA, float& resB) {
    stageA_half(As, Aglob, r0, 0, tid);
    stageA_half(As, Aglob, r0, 1, tid);

    u64 c0x = 0ull, c0y = 0ull, c1x = 0ull, c1y = 0ull;
    const float4* A4 = reinterpret_cast<const float4*>(As + (lane >> 1) * APITCH);
    const int wr = 2 * (lane & 1);       // slot row of col jA

    cp_waitg<1>();                       // W slots + A-half0 ready
    __syncthreads();
    {
        const float4* W4 = reinterpret_cast<const float4*>(myW);
#pragma unroll 16
        for (int k4 = 0; k4 < 64; k4++) {
            F4 a, w0, w1;
            a.f  = A4[k4];
            w0.f = W4[wr * 64 + k4];
            w1.f = W4[(wr + 1) * 64 + k4];
            ffma2(c0x, a.d.x, w0.d.x); ffma2(c0y, a.d.y, w0.d.y);
            ffma2(c1x, a.d.x, w1.d.x); ffma2(c1y, a.d.y, w1.d.y);
        }
    }
    cp_waitg<0>();                       // A-half1 ready
    __syncthreads();
    {
        const float4* W4 = reinterpret_cast<const float4*>(myW + WSLOT_F);
#pragma unroll 16
        for (int k4 = 0; k4 < 64; k4++) {
            F4 a, w0, w1;
            a.f  = A4[64 + k4];
            w0.f = W4[wr * 64 + k4];
            w1.f = W4[(wr + 1) * 64 + k4];
            ffma2(c0x, a.d.x, w0.d.x); ffma2(c0y, a.d.y, w0.d.y);
            ffma2(c1x, a.d.x, w1.d.x); ffma2(c1y, a.d.y, w1.d.y);
        }
    }
    resA = 2.0f * sigf(pairsum(c0x) + pairsum(c0y)) * mulA;
    resB = 2.0f * sigf(pairsum(c1x) + pairsum(c1y)) * mulB;
}

// One-time precompute of Q = QL@QR, R = RL@RR; zero h0.
__device__ void precompute(const float* QL, const float* QR,
                           const float* RL, const float* RR) {
    const int tid = (int)blockIdx.x * NT + (int)threadIdx.x;
    const int stride = GRID_BLOCKS * NT;
    for (int e = tid; e < NQP * HID * HID; e += stride) {
        int i = e >> 18;
        int rem = e & ((1 << 18) - 1);
        int m = rem >> 9, n = rem & 511;
        const float* L  = QL + i * HID * K_RANK + m * K_RANK;
        const float* Rp = QR + i * K_RANK * HID + n;
        float acc = 0.f;
#pragma unroll 8
        for (int k = 0; k < K_RANK; k++) acc = fmaf(L[k], Rp[k * HID], acc);
        g_Q[e] = acc;
    }
    for (int e = tid; e < NQP * HID * HID; e += stride) {
        int i = e >> 18;
        int rem = e & ((1 << 18) - 1);
        int n = rem >> 9, m = rem & 511;
        const float* L  = RL + i * HID * K_RANK + n * K_RANK;
        const float* Rp = RR + i * K_RANK * HID + m;
        float acc = 0.f;
#pragma unroll 8
        for (int k = 0; k < K_RANK; k++) acc = fmaf(L[k], Rp[k * HID], acc);
        g_R[e] = acc;
    }
    for (int e = tid; e < B_DIM * HID; e += stride) {
        g_h[0][e] = 0.f;
    }
}

extern "C" __global__ void __launch_bounds__(NT, 1)
mogrifier_main(const float* __restrict__ x,
               const float* __restrict__ QL, const float* __restrict__ QR,
               const float* __restrict__ RL, const float* __restrict__ RR,
               const float* __restrict__ Wih, const float* __restrict__ Whh,
               const float* __restrict__ bih, const float* __restrict__ bhh,
               float* __restrict__ out) {
    extern __shared__ float smem[];
    float* As0   = smem;               // xx / mog A tile (persists into gates)
    float* As1   = smem + ABUF;        // h tile (gates)
    float* Wring = smem + 2 * ABUF;

    const int tid  = (int)threadIdx.x;
    const int lane = tid & 31, wpid = tid >> 5;
    const int rt = blockIdx.x & 7;               // 8 rowgroups x 16 rows
    const int ct = (int)blockIdx.x >> 3;         // 16 colgroups x 32 cols
    const int r0 = rt * 16, j0 = ct * 32;
    const int jbase = j0 + 4 * wpid;
    const int jA = jbase + 2 * (lane & 1), jB = jA + 1;
    const int row = lane >> 1;
    float* myW = Wring + wpid * WWARP_F;
    unsigned int epoch = 0;

    precompute(QL, QR, RL, RR);

    const float bsA0 = bih[jA]        + bhh[jA];
    const float bsA1 = bih[512 + jA]  + bhh[512 + jA];
    const float bsA2 = bih[1024 + jA] + bhh[1024 + jA];
    const float bsA3 = bih[1536 + jA] + bhh[1536 + jA];
    const float bsB0 = bih[jB]        + bhh[jB];
    const float bsB1 = bih[512 + jB]  + bhh[512 + jB];
    const float bsB2 = bih[1024 + jB] + bhh[1024 + jB];
    const float bsB3 = bih[1536 + jB] + bhh[1536 + jB];

    const float* Q0 = g_Q;
    const float* Q1 = g_Q + HID * HID;
    const float* R0 = g_R;
    const float* R1 = g_R + HID * HID;

    const int b = r0 + row;
    const int idxA = b * HID + jA, idxB = b * HID + jB;
    const int wr = 2 * (lane & 1);

    float cA = 0.f, cB = 0.f;
    float hA = 0.f, hB = 0.f;
    float xxA, xxB;

    full_barrier(epoch);
    mogw_issue(myW, Q0, jbase, lane);           // prefetch P1 weights

    float* tail = out + (size_t)S_LEN * B_DIM * HID;

    for (int t = 0; t < S_LEN; t++) {
        float* hc = g_h[t & 1];
        float* hn = g_h[(t + 1) & 1];
        const float* xt = x + (size_t)t * B_DIM * HID;

        // P1: xx = 2*sig(h @ Q0^T) * x[t]
        float mA = __ldcs(xt + idxA);
        float mB = __ldcs(xt + idxB);
        mog_phase(As0, myW, hc, r0, lane, tid, mA, mB, xxA, xxB);
        __stcg(g_xx + idxA, xxA);
        __stcg(g_xx + idxB, xxB);
        mogw_issue(myW, R0, jbase, lane);       // prefetch P2 W
        row_barrier(epoch, rt);

        // P2: h = 2*sig(xx @ R0^T) * h
        mog_phase(As0, myW, g_xx, r0, lane, tid, hA, hB, hA, hB);
        __stcg(hc + idxA, hA);
        __stcg(hc + idxB, hB);
        mogw_issue(myW, Q1, jbase, lane);       // prefetch P3 W
        row_barrier(epoch, rt);

        // P3: xx = 2*sig(h @ Q1^T) * xx
        mog_phase(As0, myW, hc, r0, lane, tid, xxA, xxB, xxA, xxB);
        __stcg(g_xx + idxA, xxA);
        __stcg(g_xx + idxB, xxB);
        mogw_issue(myW, R1, jbase, lane);       // prefetch P4 W
        row_barrier(epoch, rt);

        // P4: h = 2*sig(xx @ R1^T) * h   (A = post-P3 xx -> As0 persists!)
        mog_phase(As0, myW, g_xx, r0, lane, tid, hA, hB, hA, hB);
        __stcg(hc + idxA, hA);
        __stcg(hc + idxB, hB);
        gw_issue(myW,           Wih, jbase, 0,   lane);   // gates W0
        gw_issue(myW + WSLOT_F, Wih, jbase, 128, lane);   // gates W1
        row_barrier(epoch, rt);

        // P5: gates = xx@Wih^T + h@Whh^T + b ; LSTM pointwise.
        // As0 still holds the post-P3 xx tile (P4 used the same data).
        {
            stageA_full(As1, hc, r0, tid);      // h tile in background

            u64 acc[8];
#pragma unroll
            for (int s = 0; s < 8; s++) acc[s] = 0ull;

            const float4* Ax =
                reinterpret_cast<const float4*>(As0 + row * APITCH);
            const float4* Ah =
                reinterpret_cast<const float4*>(As1 + row * APITCH);

#pragma unroll 1
            for (int c = 0; c < 8; c++) {
                if (c < 2)       cp_waitg<2>();
                else if (c == 7) cp_waitg<0>();
                else             cp_waitg<1>();
                __syncwarp();
                if (c == 4) __syncthreads();    // As1 fully staged
                const float4* A4 = ((c < 4) ? Ax : Ah) + (c & 3) * 32;
                const float4* W4 =
                    reinterpret_cast<const float4*>(myW + (c & 1) * WSLOT_F);
#pragma unroll 8
                for (int k4 = 0; k4 < 32; k4++) {
                    F4 a; a.f = A4[k4];
                    F4 v;
                    v.f = W4[(0 * 4 + wr) * 32 + k4];
                    ffma2(acc[0], a.d.x, v.d.x); ffma2(acc[0], a.d.y, v.d.y);
                    v.f = W4[(0 * 4 + wr + 1) * 32 + k4];
                    ffma2(acc[4], a.d.x, v.d.x); ffma2(acc[4], a.d.y, v.d.y);
                    v.f = W4[(1 * 4 + wr) * 32 + k4];
                    ffma2(acc[1], a.d.x, v.d.x); ffma2(acc[1], a.d.y, v.d.y);
                    v.f = W4[(1 * 4 + wr + 1) * 32 + k4];
                    ffma2(acc[5], a.d.x, v.d.x); ffma2(acc[5], a.d.y, v.d.y);
                    v.f = W4[(2 * 4 + wr) * 32 + k4];
                    ffma2(acc[2], a.d.x, v.d.x); ffma2(acc[2], a.d.y, v.d.y);
                    v.f = W4[(2 * 4 + wr + 1) * 32 + k4];
                    ffma2(acc[6], a.d.x, v.d.x); ffma2(acc[6], a.d.y, v.d.y);
                    v.f = W4[(3 * 4 + wr) * 32 + k4];
                    ffma2(acc[3], a.d.x, v.d.x); ffma2(acc[3], a.d.y, v.d.y);
                    v.f = W4[(3 * 4 + wr + 1) * 32 + k4];
                    ffma2(acc[7], a.d.x, v.d.x); ffma2(acc[7], a.d.y, v.d.y);
                }
                if (c + 2 < 8) {
                    int cn = c + 2;
                    gw_issue(myW + (cn & 1) * WSLOT_F,
                             (cn < 4) ? Wih : Whh, jbase,
                             (cn & 3) * 128, lane);
                }
            }

            float igA = pairsum(acc[0]) + bsA0;
            float fgA = pairsum(acc[1]) + bsA1;
            float ggA = pairsum(acc[2]) + bsA2;
            float ogA = pairsum(acc[3]) + bsA3;
            float igB = pairsum(acc[4]) + bsB0;
            float fgB = pairsum(acc[5]) + bsB1;
            float ggB = pairsum(acc[6]) + bsB2;
            float ogB = pairsum(acc[7]) + bsB3;

            cA = sigf(fgA) * cA + sigf(igA) * tanhf(ggA);
            hA = sigf(ogA) * tanhf(cA);
            cB = sigf(fgB) * cB + sigf(igB) * tanhf(ggB);
            hB = sigf(ogB) * tanhf(cB);

            __stcg(hn + idxA, hA);
            __stcg(hn + idxB, hB);
            float* op = out + (size_t)t * B_DIM * HID;
            op[idxA] = hA;
            op[idxB] = hB;
            if (t == S_LEN - 1) {
                tail[idxA] = hA;  tail[B_DIM * HID + idxA] = cA;
                tail[idxB] = hB;  tail[B_DIM * HID + idxB] = cB;
            }
        }
        mogw_issue(myW, Q0, jbase, lane);       // prefetch next-step P1 W
        row_barrier(epoch, rt);
    }
    cp_waitg<0>();                               // drain dangling prefetch
}

extern "C" void kernel_launch(void* const* d_in, const int* in_sizes, int n_in,
                              void* d_out, int out_size) {
    const float* x   = (const float*)d_in[0];
    const float* QL  = (const float*)d_in[1];
    const float* QR  = (const float*)d_in[2];
    const float* RL  = (const float*)d_in[3];
    const float* RR  = (const float*)d_in[4];
    const float* Wih = (const float*)d_in[5];
    const float* Whh = (const float*)d_in[6];
    const float* bih = (const float*)d_in[7];
    const float* bhh = (const float*)d_in[8];
    (void)in_sizes; (void)n_in; (void)out_size;

    cudaFuncSetAttribute(mogrifier_main,
                         cudaFuncAttributeMaxDynamicSharedMemorySize, SMEM_BYTES);

    mg_init<<<1, 128>>>();
    mogrifier_main<<<GRID_BLOCKS, NT, SMEM_BYTES>>>(x, QL, QR, RL, RR,
                                                    Wih, Whh, bih, bhh,
                                                    (float*)d_out);
}

// round 12
// speedup vs baseline: 1.2518x; 1.2518x over previous
#include <cuda_runtime.h>

// ---------------------------------------------------------------------------
// MogrifierRNN persistent kernel, round 11.  (base = round 9, best so far)
//   - 32x16 block tile (4 rowgroups x 32 colgroups) -- traffic optimum
//   - row-group barriers now DIRECT-POLL (no leader/go round-trip)
//   - gates reuses P4's A tile (post-P3 xx) -- no As0 restage in P5
//   - per-warp private weight streaming, cross-barrier prefetch, FFMA2,
//     register-resident c / h / xx
// ---------------------------------------------------------------------------

#define S_LEN 512
#define B_DIM 128
#define HID   512
#define K_RANK 256
#define NQP   2

#define GRID_BLOCKS 128
#define NT          256
#define APITCH      516                 // conflict-free LDS.128 pitch
#define ABUF        (32 * APITCH)       // 16512 floats = 66,048 B
#define WSLOT_F     1024                // 4KB slot
#define WWARP_F     (2 * WSLOT_F)       // 2 slots per warp
#define WRING_F     (8 * WWARP_F)       // 64KB
#define SMEM_FLOATS (2 * ABUF + WRING_F)        // 49408
#define SMEM_BYTES  (SMEM_FLOATS * 4)           // 197,632 B
#define BAR_STRIDE  32

typedef unsigned long long u64;

// ------------------------- device scratch ----------------------------------
__device__ float g_Q[NQP * HID * HID];   // Q[i][m][n]
__device__ float g_R[NQP * HID * HID];   // R[i][n][m]
__device__ float g_xx[B_DIM * HID];
__device__ float g_h[2][B_DIM * HID];
__device__ unsigned int g_arrive[GRID_BLOCKS * BAR_STRIDE];
__device__ unsigned int g_go_full;

__global__ void mg_init() {
    int i = (int)threadIdx.x;
    if (i < GRID_BLOCKS) g_arrive[i * BAR_STRIDE] = 0u;
    if (i == 0) g_go_full = 0u;
}

__device__ __forceinline__ float sigf(float v) {
    return 1.0f / (1.0f + __expf(-v));
}

// ---- packed fp32x2 FMA ------------------------------------------------------
union F4 { float4 f; ulonglong2 d; };

__device__ __forceinline__ void ffma2(u64& acc, u64 a, u64 b) {
    asm("fma.rn.f32x2 %0, %1, %2, %0;" : "+l"(acc) : "l"(a), "l"(b));
}
__device__ __forceinline__ float pairsum(u64 p) {
    return __uint_as_float((unsigned)p) + __uint_as_float((unsigned)(p >> 32));
}

// ---- cp.async ---------------------------------------------------------------
__device__ __forceinline__ void cpa16(float* dst_smem, const float* src) {
    unsigned d = (unsigned)__cvta_generic_to_shared(dst_smem);
    asm volatile("cp.async.cg.shared.global [%0], [%1], 16;"
                 :: "r"(d), "l"(src) : "memory");
}
__device__ __forceinline__ void cp_commit() {
    asm volatile("cp.async.commit_group;" ::: "memory");
}
template <int N> __device__ __forceinline__ void cp_waitg() {
    asm volatile("cp.async.wait_group %0;" :: "n"(N) : "memory");
}

// ---- barriers ---------------------------------------------------------------
__device__ __forceinline__ unsigned int ld_acq(const unsigned int* p) {
    unsigned int v;
    asm volatile("ld.acquire.gpu.global.u32 %0, [%1];"
                 : "=r"(v) : "l"(p) : "memory");
    return v;
}
__device__ __forceinline__ void st_rel(unsigned int* p, unsigned int v) {
    asm volatile("st.release.gpu.global.u32 [%0], %1;"
                 :: "l"(p), "r"(v) : "memory");
}

// Row-group barrier: the 32 blocks sharing rt (= blockIdx.x & 3).
// Direct-poll: each block arrives, 32 threads poll the 32 member flags.
__device__ __forceinline__ void row_barrier(unsigned int& epoch, int rt) {
    epoch++;
    __syncthreads();
    if (threadIdx.x == 0) st_rel(&g_arrive[blockIdx.x * BAR_STRIDE], epoch);
    if (threadIdx.x < 32) {
        while (ld_acq(&g_arrive[(rt + 4 * threadIdx.x) * BAR_STRIDE]) < epoch) { }
    }
    __syncthreads();
}

// Full-grid barrier (used once, after precompute).
__device__ __forceinline__ void full_barrier(unsigned int& epoch) {
    epoch++;
    __syncthreads();
    if (blockIdx.x == 0) {
        if (threadIdx.x == 0) st_rel(&g_arrive[0], epoch);
        if (threadIdx.x < GRID_BLOCKS) {
            while (ld_acq(&g_arrive[threadIdx.x * BAR_STRIDE]) < epoch) { }
        }
        __syncthreads();
        if (threadIdx.x == 0) st_rel(&g_go_full, epoch);
    } else {
        if (threadIdx.x == 0) {
            st_rel(&g_arrive[blockIdx.x * BAR_STRIDE], epoch);
            while (ld_acq(&g_go_full) < epoch) { }
        }
        __syncthreads();
    }
}

// ---- staging ----------------------------------------------------------------
// A k-half: rows [r0,r0+32) x k[256h,256h+256). One group; 8 cpa16/thread.
__device__ __forceinline__ void stageA_half(float* As, const float* A,
                                            int r0, int half, int tid) {
#pragma unroll
    for (int i = 0; i < 8; i++) {
        int e = i * NT + tid;          // 0..2047 f4
        int row = e >> 6, q = e & 63;
        cpa16(As + row * APITCH + half * 256 + q * 4,
              A + (r0 + row) * HID + half * 256 + q * 4);
    }
    cp_commit();
}
// A full tile: one group; 16 cpa16/thread.
__device__ __forceinline__ void stageA_full(float* As, const float* A,
                                            int r0, int tid) {
#pragma unroll
    for (int i = 0; i < 16; i++) {
        int e = i * NT + tid;
        int row = e >> 7, q = e & 127;
        cpa16(As + row * APITCH + q * 4, A + (r0 + row) * HID + q * 4);
    }
    cp_commit();
}

// Mog W prefetch: this warp's 2 rows (jA,jB), both 256-k chunks (2 groups).
// Slot s: row jA at f4 [0,64), row jB at f4 [64,128), k = [256s, 256s+256).
__device__ __forceinline__ void mogw_issue(float* myW, const float* W,
                                           int jA, int jB, int lane) {
#pragma unroll
    for (int s = 0; s < 2; s++) {
        float* slot = myW + s * WSLOT_F;
#pragma unroll
        for (int i = 0; i < 4; i++) {
            int f = lane + 32 * i;           // 0..127 f4
            int rr = f >> 6, q = f & 63;
            int row = rr ? jB : jA;
            cpa16(slot + f * 4, W + row * HID + s * 256 + q * 4);
        }
        cp_commit();
    }
}

// Gates W chunk: 8 rows (4 gates x cols jA,jB) x 128 k. One group; 8/lane.
// Slot: row rr = g*2+ab at f4 [rr*32, rr*32+32).
__device__ __forceinline__ void gw_issue(float* slot, const float* Wsrc,
                                         int jA, int jB, int kc, int lane) {
#pragma unroll
    for (int i = 0; i < 8; i++) {
        int f = lane + 32 * i;               // 0..255 f4
        int rr = f >> 5, q = f & 31;
        int g = rr >> 1;
        int col = (rr & 1) ? jB : jA;
        cpa16(slot + f * 4, Wsrc + (g * HID + col) * HID + kc + q * 4);
    }
    cp_commit();
}

// Mogrifier phase. Entering: this phase's W (2 groups) already issued.
__device__ __forceinline__ void mog_phase(float* As, float* myW,
                                          const float* Aglob, int r0,
                                          int lane, int tid,
                                          float mulA, float mulB,
                                          float& resA, float& resB) {
    stageA_half(As, Aglob, r0, 0, tid);
    stageA_half(As, Aglob, r0, 1, tid);

    u64 c0x = 0ull, c0y = 0ull, c1x = 0ull, c1y = 0ull;
    const float4* A4 = reinterpret_cast<const float4*>(As + lane * APITCH);

    cp_waitg<1>();                 // W0, W1, A-half0 done; A-half1 pending
    __syncthreads();
    {
        const float4* W4 = reinterpret_cast<const float4*>(myW);
#pragma unroll 16
        for (int k4 = 0; k4 < 64; k4++) {
            F4 a, w0, w1;
            a.f  = A4[k4];
            w0.f = W4[k4];
            w1.f = W4[64 + k4];
            ffma2(c0x, a.d.x, w0.d.x); ffma2(c0y, a.d.y, w0.d.y);
            ffma2(c1x, a.d.x, w1.d.x); ffma2(c1y, a.d.y, w1.d.y);
        }
    }
    cp_waitg<0>();                 // A-half1 done
    __syncthreads();
    {
        const float4* W4 = reinterpret_cast<const float4*>(myW + WSLOT_F);
#pragma unroll 16
        for (int k4 = 0; k4 < 64; k4++) {
            F4 a, w0, w1;
            a.f  = A4[64 + k4];
            w0.f = W4[k4];
            w1.f = W4[64 + k4];
            ffma2(c0x, a.d.x, w0.d.x); ffma2(c0y, a.d.y, w0.d.y);
            ffma2(c1x, a.d.x, w1.d.x); ffma2(c1y, a.d.y, w1.d.y);
        }
    }
    resA = 2.0f * sigf(pairsum(c0x) + pairsum(c0y)) * mulA;
    resB = 2.0f * sigf(pairsum(c1x) + pairsum(c1y)) * mulB;
}

// One-time precompute of Q = QL@QR, R = RL@RR; zero h0.
__device__ void precompute(const float* QL, const float* QR,
                           const float* RL, const float* RR) {
    const int tid = (int)blockIdx.x * NT + (int)threadIdx.x;
    const int stride = GRID_BLOCKS * NT;
    for (int e = tid; e < NQP * HID * HID; e += stride) {
        int i = e >> 18;
        int rem = e & ((1 << 18) - 1);
        int m = rem >> 9, n = rem & 511;
        const float* L  = QL + i * HID * K_RANK + m * K_RANK;
        const float* Rp = QR + i * K_RANK * HID + n;
        float acc = 0.f;
#pragma unroll 8
        for (int k = 0; k < K_RANK; k++) acc = fmaf(L[k], Rp[k * HID], acc);
        g_Q[e] = acc;
    }
    for (int e = tid; e < NQP * HID * HID; e += stride) {
        int i = e >> 18;
        int rem = e & ((1 << 18) - 1);
        int n = rem >> 9, m = rem & 511;
        const float* L  = RL + i * HID * K_RANK + n * K_RANK;
        const float* Rp = RR + i * K_RANK * HID + m;
        float acc = 0.f;
#pragma unroll 8
        for (int k = 0; k < K_RANK; k++) acc = fmaf(L[k], Rp[k * HID], acc);
        g_R[e] = acc;
    }
    for (int e = tid; e < B_DIM * HID; e += stride) {
        g_h[0][e] = 0.f;
    }
}

extern "C" __global__ void __launch_bounds__(NT, 1)
mogrifier_main(const float* __restrict__ x,
               const float* __restrict__ QL, const float* __restrict__ QR,
               const float* __restrict__ RL, const float* __restrict__ RR,
               const float* __restrict__ Wih, const float* __restrict__ Whh,
               const float* __restrict__ bih, const float* __restrict__ bhh,
               float* __restrict__ out) {
    extern __shared__ float smem[];
    float* As0   = smem;               // xx / mog A tile (persists into gates)
    float* As1   = smem + ABUF;        // h tile (gates)
    float* Wring = smem + 2 * ABUF;

    const int tid  = (int)threadIdx.x;
    const int lane = tid & 31, wpid = tid >> 5;
    const int rt = blockIdx.x & 3, ct = (int)blockIdx.x >> 2;
    const int r0 = rt * 32, j0 = ct * 16;
    const int jA = j0 + 2 * wpid, jB = jA + 1;
    float* myW = Wring + wpid * WWARP_F;
    unsigned int epoch = 0;

    precompute(QL, QR, RL, RR);

    const float bsA0 = bih[jA]        + bhh[jA];
    const float bsA1 = bih[512 + jA]  + bhh[512 + jA];
    const float bsA2 = bih[1024 + jA] + bhh[1024 + jA];
    const float bsA3 = bih[1536 + jA] + bhh[1536 + jA];
    const float bsB0 = bih[jB]        + bhh[jB];
    const float bsB1 = bih[512 + jB]  + bhh[512 + jB];
    const float bsB2 = bih[1024 + jB] + bhh[1024 + jB];
    const float bsB3 = bih[1536 + jB] + bhh[1536 + jB];

    const float* Q0 = g_Q;
    const float* Q1 = g_Q + HID * HID;
    const float* R0 = g_R;
    const float* R1 = g_R + HID * HID;

    const int b = r0 + lane;
    const int idxA = b * HID + jA, idxB = b * HID + jB;

    float cA = 0.f, cB = 0.f;
    float hA = 0.f, hB = 0.f;
    float xxA, xxB;

    full_barrier(epoch);                 // Q/R ready everywhere
    mogw_issue(myW, Q0, jA, jB, lane);   // prefetch P1 weights

    float* tail = out + (size_t)S_LEN * B_DIM * HID;

    for (int t = 0; t < S_LEN; t++) {
        float* hc = g_h[t & 1];
        float* hn = g_h[(t + 1) & 1];
        const float* xt = x + (size_t)t * B_DIM * HID;

        // P1: xx = 2*sig(h @ Q0^T) * x[t]
        float mA = __ldcs(xt + idxA);
        float mB = __ldcs(xt + idxB);
        mog_phase(As0, myW, hc, r0, lane, tid, mA, mB, xxA, xxB);
        __stcg(g_xx + idxA, xxA);
        __stcg(g_xx + idxB, xxB);
        mogw_issue(myW, R0, jA, jB, lane);        // prefetch P2 W
        row_barrier(epoch, rt);

        // P2: h = 2*sig(xx @ R0^T) * h
        mog_phase(As0, myW, g_xx, r0, lane, tid, hA, hB, hA, hB);
        __stcg(hc + idxA, hA);
        __stcg(hc + idxB, hB);
        mogw_issue(myW, Q1, jA, jB, lane);        // prefetch P3 W
        row_barrier(epoch, rt);

        // P3: xx = 2*sig(h @ Q1^T) * xx
        mog_phase(As0, myW, hc, r0, lane, tid, xxA, xxB, xxA, xxB);
        __stcg(g_xx + idxA, xxA);
        __stcg(g_xx + idxB, xxB);
        mogw_issue(myW, R1, jA, jB, lane);        // prefetch P4 W
        row_barrier(epoch, rt);

        // P4: h = 2*sig(xx @ R1^T) * h   (A = post-P3 xx -> As0 persists)
        mog_phase(As0, myW, g_xx, r0, lane, tid, hA, hB, hA, hB);
        __stcg(hc + idxA, hA);
        __stcg(hc + idxB, hB);
        gw_issue(myW,           Wih, jA, jB, 0,   lane);   // gates W0
        gw_issue(myW + WSLOT_F, Wih, jA, jB, 128, lane);   // gates W1
        row_barrier(epoch, rt);

        // P5: gates = xx@Wih^T + h@Whh^T + b ; LSTM pointwise.
        // As0 still holds the post-P3 xx tile (P4 staged the same data).
        {
            stageA_full(As1, hc, r0, tid);        // h tile in background

            u64 acc[8];
#pragma unroll
            for (int s = 0; s < 8; s++) acc[s] = 0ull;

            cp_waitg<1>();      // Wg0, Wg1 done (all lanes after syncwarp)
            __syncwarp();

#pragma unroll 1
            for (int c = 0; c < 8; c++) {
                if (c == 4) __syncthreads();      // As1 collectively staged
                if (c >= 2) {
                    if (c == 7) cp_waitg<0>(); else cp_waitg<1>();
                    __syncwarp();
                }
                const float* Atile = (c < 4) ? As0 : As1;
                const float4* A4 =
                    reinterpret_cast<const float4*>(Atile + lane * APITCH) + (c & 3) * 32;
                const float4* W4 =
                    reinterpret_cast<const float4*>(myW + (c & 1) * WSLOT_F);
#pragma unroll 8
                for (int k4 = 0; k4 < 32; k4++) {
                    F4 a; a.f = A4[k4];
                    F4 v;
                    v.f = W4[0 * 32 + k4];
                    ffma2(acc[0], a.d.x, v.d.x); ffma2(acc[0], a.d.y, v.d.y);
                    v.f = W4[1 * 32 + k4];
                    ffma2(acc[4], a.d.x, v.d.x); ffma2(acc[4], a.d.y, v.d.y);
                    v.f = W4[2 * 32 + k4];
                    ffma2(acc[1], a.d.x, v.d.x); ffma2(acc[1], a.d.y, v.d.y);
                    v.f = W4[3 * 32 + k4];
                    ffma2(acc[5], a.d.x, v.d.x); ffma2(acc[5], a.d.y, v.d.y);
                    v.f = W4[4 * 32 + k4];
                    ffma2(acc[2], a.d.x, v.d.x); ffma2(acc[2], a.d.y, v.d.y);
                    v.f = W4[5 * 32 + k4];
                    ffma2(acc[6], a.d.x, v.d.x); ffma2(acc[6], a.d.y, v.d.y);
                    v.f = W4[6 * 32 + k4];
                    ffma2(acc[3], a.d.x, v.d.x); ffma2(acc[3], a.d.y, v.d.y);
                    v.f = W4[7 * 32 + k4];
                    ffma2(acc[7], a.d.x, v.d.x); ffma2(acc[7], a.d.y, v.d.y);
                }
                if (c + 2 < 8) {
                    int cn = c + 2;
                    const float* Wsrc = (cn < 4) ? Wih : Whh;
                    gw_issue(myW + (cn & 1) * WSLOT_F, Wsrc, jA, jB,
                             (cn & 3) * 128, lane);
                }
            }

            float igA = pairsum(acc[0]) + bsA0;
            float fgA = pairsum(acc[1]) + bsA1;
            float ggA = pairsum(acc[2]) + bsA2;
            float ogA = pairsum(acc[3]) + bsA3;
            float igB = pairsum(acc[4]) + bsB0;
            float fgB = pairsum(acc[5]) + bsB1;
            float ggB = pairsum(acc[6]) + bsB2;
            float ogB = pairsum(acc[7]) + bsB3;

            cA = sigf(fgA) * cA + sigf(igA) * tanhf(ggA);
            hA = sigf(ogA) * tanhf(cA);
            cB = sigf(fgB) * cB + sigf(igB) * tanhf(ggB);
            hB = sigf(ogB) * tanhf(cB);

            __stcg(hn + idxA, hA);
            __stcg(hn + idxB, hB);
            float* op = out + (size_t)t * B_DIM * HID;
            op[idxA] = hA;
            op[idxB] = hB;
            if (t == S_LEN - 1) {
                tail[idxA] = hA;  tail[B_DIM * HID + idxA] = cA;
                tail[idxB] = hB;  tail[B_DIM * HID + idxB] = cB;
            }
        }
        mogw_issue(myW, Q0, jA, jB, lane);        // prefetch next-step P1 W
        row_barrier(epoch, rt);
    }
    cp_waitg<0>();                                 // drain dangling prefetch
}

extern "C" void kernel_launch(void* const* d_in, const int* in_sizes, int n_in,
                              void* d_out, int out_size) {
    const float* x   = (const float*)d_in[0];
    const float* QL  = (const float*)d_in[1];
    const float* QR  = (const float*)d_in[2];
    const float* RL  = (const float*)d_in[3];
    const float* RR  = (const float*)d_in[4];
    const float* Wih = (const float*)d_in[5];
    const float* Whh = (const float*)d_in[6];
    const float* bih = (const float*)d_in[7];
    const float* bhh = (const float*)d_in[8];
    (void)in_sizes; (void)n_in; (void)out_size;

    cudaFuncSetAttribute(mogrifier_main,
                         cudaFuncAttributeMaxDynamicSharedMemorySize, SMEM_BYTES);

    mg_init<<<1, 128>>>();
    mogrifier_main<<<GRID_BLOCKS, NT, SMEM_BYTES>>>(x, QL, QR, RL, RR,
                                                    Wih, Whh, bih, bhh,
                                                    (float*)d_out);
}